// round 13
// baseline (speedup 1.0000x reference)
#include <cuda_runtime.h>
#include <cuda_fp16.h>
#include <cstdint>

#define HIDDEN   1024
#define NLAYERS  20
#define M_TOTAL  8192

// ---- GEMM tiling (fp16 HMMA m16n8k16) ----
#define BM 128
#define BN 128
#define BKH 64                    // K per tile, in halves -> 128B smem rows
#define KT (HIDDEN/BKH)           // 16
#define ROWB 128
#define A_STAGE (BM*ROWB)         // 16384 B
#define B_STAGE (BN*ROWB)         // 16384 B
#define STAGE   (A_STAGE+B_STAGE) // 32768 B
#define STAGES  3
#define SMEM_BYTES (STAGES*STAGE) // 98304 B -> 2 CTAs/SM

#define WSUM_BLOCKS (HIDDEN*HIDDEN/1024)        // 1024
#define X_BLOCKS    (M_TOTAL*HIDDEN/8192)       // 1024 (8 float4 per thread)

__device__ __half g_wsum[HIDDEN*HIDDEN];     // 2 MB  (pre-summed weights, fp16)
__device__ __half g_ax[M_TOTAL*HIDDEN];      // 16 MB (activations, fp16)

// ---------------------------------------------------------------------------
__device__ __forceinline__ uint32_t smem_u32(const void* p) {
    uint32_t a;
    asm("{ .reg .u64 t; cvta.to.shared.u64 t, %1; cvt.u32.u64 %0, t; }" : "=r"(a) : "l"(p));
    return a;
}
__device__ __forceinline__ void cp16(uint32_t saddr, const void* g) {
    asm volatile("cp.async.cg.shared.global [%0], [%1], 16;" :: "r"(saddr), "l"(g));
}
__device__ __forceinline__ uint32_t f2_to_h2(float lo, float hi) {
    uint32_t r;
    asm("cvt.rn.f16x2.f32 %0, %1, %2;" : "=r"(r) : "f"(hi), "f"(lo));
    return r;
}
// streaming (evict-first) float4 load for read-once data
__device__ __forceinline__ float4 ldcs4(const float4* p) {
    float4 v;
    asm volatile("ld.global.cs.v4.f32 {%0,%1,%2,%3}, [%4];"
                 : "=f"(v.x), "=f"(v.y), "=f"(v.z), "=f"(v.w) : "l"(p));
    return v;
}
// streaming (evict-first) float4 store for write-once data
__device__ __forceinline__ void stcs4(float4* p, float4 v) {
    asm volatile("st.global.cs.v4.f32 [%0], {%1,%2,%3,%4};"
                 :: "l"(p), "f"(v.x), "f"(v.y), "f"(v.z), "f"(v.w) : "memory");
}

// ---------------------------------------------------------------------------
// Kernel 0 (fused prep):
//   blocks [0, 1024):    g_wsum = fp16(mean_l conv_w[l])   (long blocks first)
//   blocks [1024, 2048): g_ax  = fp16(x), 8 float4/thread  (MLP=8)
// ---------------------------------------------------------------------------
__global__ void __launch_bounds__(256)
prep_kernel(const float* __restrict__ x, const float* __restrict__ cw) {
    const int b = blockIdx.x, t = threadIdx.x;
    if (b < WSUM_BLOCKS) {
        const int i4 = b * 256 + t;                    // 0..262143
        const float4* cw4 = (const float4*)cw;
        float4 a0 = ldcs4(&cw4[i4]);
        float4 a1 = ldcs4(&cw4[(HIDDEN*HIDDEN/4) + i4]);
#pragma unroll
        for (int l = 2; l < NLAYERS; l += 2) {
            float4 v0 = ldcs4(&cw4[l       * (HIDDEN*HIDDEN/4) + i4]);
            float4 v1 = ldcs4(&cw4[(l + 1) * (HIDDEN*HIDDEN/4) + i4]);
            a0.x += v0.x; a0.y += v0.y; a0.z += v0.z; a0.w += v0.w;
            a1.x += v1.x; a1.y += v1.y; a1.z += v1.z; a1.w += v1.w;
        }
        const float s = 1.0f / (float)NLAYERS;
        uint2 h;
        h.x = f2_to_h2((a0.x + a1.x) * s, (a0.y + a1.y) * s);
        h.y = f2_to_h2((a0.z + a1.z) * s, (a0.w + a1.w) * s);
        ((uint2*)g_wsum)[i4] = h;
    } else {
        // 8 independent float4 per thread (front-batched -> MLP=8)
        const int base = (b - WSUM_BLOCKS) * 2048 + t;   // float4 index base
        float4 v[8];
#pragma unroll
        for (int i = 0; i < 8; ++i)
            v[i] = ldcs4(&((const float4*)x)[base + i * 256]);
#pragma unroll
        for (int i = 0; i < 8; ++i) {
            uint2 h;
            h.x = f2_to_h2(v[i].x, v[i].y);
            h.y = f2_to_h2(v[i].z, v[i].w);
            ((uint2*)g_ax)[base + i * 256] = h;
        }
    }
}

// ---------------------------------------------------------------------------
// Kernel 1: fp16 GEMM  out[m][n] = sum_k Ax[m][k] * Wsum[n][k]
//   (byte-identical to the proven 62us R3 mainloop)
// ---------------------------------------------------------------------------
__global__ void __launch_bounds__(256, 2)
gemm_kernel(float* __restrict__ out) {
    extern __shared__ char smem[];
    const uint32_t sbase = smem_u32(smem);

    const int tid  = threadIdx.x;
    const int lane = tid & 31;
    const int warp = tid >> 5;
    const int wm   = (warp & 1) * 64;
    const int wn   = (warp >> 1) * 32;
    const int mBase = blockIdx.y * BM;
    const int nBase = blockIdx.x * BN;

    float acc[4][4][4];
#pragma unroll
    for (int mi = 0; mi < 4; ++mi)
#pragma unroll
        for (int ni = 0; ni < 4; ++ni)
#pragma unroll
            for (int c = 0; c < 4; ++c) acc[mi][ni][c] = 0.0f;

    auto load_stage = [&](int s, int k0h) {
        const uint32_t sa = sbase + (uint32_t)s * STAGE;
        const uint32_t sb = sa + A_STAGE;
#pragma unroll
        for (int i = 0; i < 4; ++i) {
            const int c = i * 256 + tid;          // 0..1023
            const int row = c >> 3, ch = c & 7;
            const uint32_t off = (uint32_t)c * 16u;
            cp16(sa + (off ^ ((off >> 3) & 0x70u)),
                 g_ax + (size_t)(mBase + row) * HIDDEN + k0h + ch * 8);
        }
#pragma unroll
        for (int i = 0; i < 4; ++i) {
            const int c = i * 256 + tid;
            const int row = c >> 3, ch = c & 7;
            const uint32_t off = (uint32_t)c * 16u;
            cp16(sb + (off ^ ((off >> 3) & 0x70u)),
                 g_wsum + (size_t)(nBase + row) * HIDDEN + k0h + ch * 8);
        }
        asm volatile("cp.async.commit_group;");
    };

    load_stage(0, 0);
    load_stage(1, BKH);

    for (int kt = 0; kt < KT; ++kt) {
        asm volatile("cp.async.wait_group 1;");
        __syncthreads();
        if (kt + 2 < KT) load_stage((kt + 2) % STAGES, (kt + 2) * BKH);
        else             asm volatile("cp.async.commit_group;");

        const uint32_t sa = sbase + (uint32_t)(kt % STAGES) * STAGE;
        const uint32_t sb = sa + A_STAGE;

#pragma unroll
        for (int kk = 0; kk < 4; ++kk) {
            const uint32_t colb = (uint32_t)(kk * 32 + (lane >> 4) * 16);
            uint32_t af[4][4], bf[2][4];
#pragma unroll
            for (int mi = 0; mi < 4; ++mi) {
                const uint32_t off = (uint32_t)(wm + mi * 16 + (lane & 15)) * ROWB + colb;
                const uint32_t addr = sa + (off ^ ((off >> 3) & 0x70u));
                asm volatile("ldmatrix.sync.aligned.m8n8.x4.shared.b16 {%0,%1,%2,%3}, [%4];"
                             : "=r"(af[mi][0]), "=r"(af[mi][1]), "=r"(af[mi][2]), "=r"(af[mi][3])
                             : "r"(addr));
            }
#pragma unroll
            for (int np = 0; np < 2; ++np) {
                const uint32_t off = (uint32_t)(wn + np * 16 + (lane & 15)) * ROWB + colb;
                const uint32_t addr = sb + (off ^ ((off >> 3) & 0x70u));
                asm volatile("ldmatrix.sync.aligned.m8n8.x4.shared.b16 {%0,%1,%2,%3}, [%4];"
                             : "=r"(bf[np][0]), "=r"(bf[np][1]), "=r"(bf[np][2]), "=r"(bf[np][3])
                             : "r"(addr));
            }
#pragma unroll
            for (int mi = 0; mi < 4; ++mi) {
#pragma unroll
                for (int np = 0; np < 2; ++np) {
                    asm volatile(
                        "mma.sync.aligned.m16n8k16.row.col.f32.f16.f16.f32 "
                        "{%0,%1,%2,%3}, {%4,%5,%6,%7}, {%8,%9}, {%0,%1,%2,%3};"
                        : "+f"(acc[mi][np*2][0]), "+f"(acc[mi][np*2][1]),
                          "+f"(acc[mi][np*2][2]), "+f"(acc[mi][np*2][3])
                        : "r"(af[mi][0]), "r"(af[mi][1]), "r"(af[mi][2]), "r"(af[mi][3]),
                          "r"(bf[np][0]), "r"(bf[np][2]));
                    asm volatile(
                        "mma.sync.aligned.m16n8k16.row.col.f32.f16.f16.f32 "
                        "{%0,%1,%2,%3}, {%4,%5,%6,%7}, {%8,%9}, {%0,%1,%2,%3};"
                        : "+f"(acc[mi][np*2+1][0]), "+f"(acc[mi][np*2+1][1]),
                          "+f"(acc[mi][np*2+1][2]), "+f"(acc[mi][np*2+1][3])
                        : "r"(af[mi][0]), "r"(af[mi][1]), "r"(af[mi][2]), "r"(af[mi][3]),
                          "r"(bf[np][1]), "r"(bf[np][3]));
                }
            }
        }
    }

    // epilogue
    const int r0 = mBase + wm + (lane >> 2);
    const int c0 = nBase + wn + (lane & 3) * 2;
#pragma unroll
    for (int mi = 0; mi < 4; ++mi) {
#pragma unroll
        for (int ni = 0; ni < 4; ++ni) {
            const int r = r0 + mi * 16;
            const int c = c0 + ni * 8;
            *(float2*)(out + (size_t)r * HIDDEN + c)       = make_float2(acc[mi][ni][0], acc[mi][ni][1]);
            *(float2*)(out + (size_t)(r + 8) * HIDDEN + c) = make_float2(acc[mi][ni][2], acc[mi][ni][3]);
        }
    }
}

// ---------------------------------------------------------------------------
// Kernel 2: in-place RMS-norm, 4 rows per 512-thread block (128 threads/row)
//   x * sqrt(H) / sqrt(sum x^2 + EPS*H) * w    (final stores streamed)
// ---------------------------------------------------------------------------
__global__ void __launch_bounds__(512)
rmsnorm_kernel(float* __restrict__ out, const float* __restrict__ nw) {
    const int rg  = threadIdx.x >> 7;        // row group within block: 0..3
    const int t   = threadIdx.x & 127;       // thread within row: 0..127
    const int row = blockIdx.x * 4 + rg;

    float4* p = (float4*)(out + (size_t)row * HIDDEN);
    float4 v0 = p[t];
    float4 v1 = p[t + 128];

    float ss = v0.x*v0.x + v0.y*v0.y + v0.z*v0.z + v0.w*v0.w
             + v1.x*v1.x + v1.y*v1.y + v1.z*v1.z + v1.w*v1.w;
#pragma unroll
    for (int o = 16; o > 0; o >>= 1) ss += __shfl_xor_sync(0xFFFFFFFFu, ss, o);

    __shared__ float sred[16];                // 4 rows x 4 warps
    if ((t & 31) == 0) sred[rg * 4 + (t >> 5)] = ss;
    __syncthreads();
    const float tot = sred[rg*4+0] + sred[rg*4+1] + sred[rg*4+2] + sred[rg*4+3];
    const float sc  = 32.0f * rsqrtf(tot + 1.024e-3f);   // sqrt(H)/sqrt(ss+EPS*H)

    const float4 w0 = __ldg(&((const float4*)nw)[t]);
    const float4 w1 = __ldg(&((const float4*)nw)[t + 128]);
    v0.x *= sc * w0.x; v0.y *= sc * w0.y; v0.z *= sc * w0.z; v0.w *= sc * w0.w;
    v1.x *= sc * w1.x; v1.y *= sc * w1.y; v1.z *= sc * w1.z; v1.w *= sc * w1.w;
    stcs4(&p[t],       v0);                   // write-once: stream past L2
    stcs4(&p[t + 128], v1);
}

// ---------------------------------------------------------------------------
extern "C" void kernel_launch(void* const* d_in, const int* in_sizes, int n_in,
                              void* d_out, int out_size) {
    const float* x  = (const float*)d_in[0];   // [2,4096,1024] fp32
    const float* cw = (const float*)d_in[1];   // [20,1024,1024] fp32
    const float* nw = (const float*)d_in[2];   // [1024] fp32
    float* out = (float*)d_out;                // [2,4096,1024] fp32
    (void)in_sizes; (void)n_in; (void)out_size;

    prep_kernel<<<WSUM_BLOCKS + X_BLOCKS, 256>>>(x, cw);   // 2048 blocks

    cudaFuncSetAttribute(gemm_kernel, cudaFuncAttributeMaxDynamicSharedMemorySize, SMEM_BYTES);
    dim3 grid(HIDDEN / BN, M_TOTAL / BM);   // (8, 64) = 512 CTAs
    gemm_kernel<<<grid, 256, SMEM_BYTES>>>(out);

    rmsnorm_kernel<<<M_TOTAL / 4, 512>>>(out, nw);
}

// round 14
// speedup vs baseline: 1.0159x; 1.0159x over previous
#include <cuda_runtime.h>
#include <cuda_fp16.h>
#include <cstdint>

#define HIDDEN   1024
#define NLAYERS  20
#define M_TOTAL  8192

// ---- GEMM tiling (fp16 HMMA m16n8k16) ----
#define BM 128
#define BN 128
#define BKH 64                    // K per tile, in halves -> 128B smem rows
#define KT (HIDDEN/BKH)           // 16
#define ROWB 128
#define A_STAGE (BM*ROWB)         // 16384 B
#define B_STAGE (BN*ROWB)         // 16384 B
#define STAGE   (A_STAGE+B_STAGE) // 32768 B
#define STAGES  3
#define SMEM_BYTES (STAGES*STAGE) // 98304 B -> 2 CTAs/SM

#define WSUM_BLOCKS (HIDDEN*HIDDEN/1024)        // 1024
#define X_BLOCKS    (M_TOTAL*HIDDEN/8192)       // 1024 (8 float4 per thread)

__device__ __half g_wsum[HIDDEN*HIDDEN];     // 2 MB  (pre-summed weights, fp16)
__device__ __half g_ax[M_TOTAL*HIDDEN];      // 16 MB (activations, fp16)

// ---------------------------------------------------------------------------
__device__ __forceinline__ uint32_t smem_u32(const void* p) {
    uint32_t a;
    asm("{ .reg .u64 t; cvta.to.shared.u64 t, %1; cvt.u32.u64 %0, t; }" : "=r"(a) : "l"(p));
    return a;
}
__device__ __forceinline__ void cp16(uint32_t saddr, const void* g) {
    asm volatile("cp.async.cg.shared.global [%0], [%1], 16;" :: "r"(saddr), "l"(g));
}
__device__ __forceinline__ uint32_t f2_to_h2(float lo, float hi) {
    uint32_t r;
    asm("cvt.rn.f16x2.f32 %0, %1, %2;" : "=r"(r) : "f"(hi), "f"(lo));
    return r;
}
// streaming (evict-first) float4 load for read-once data
__device__ __forceinline__ float4 ldcs4(const float4* p) {
    float4 v;
    asm volatile("ld.global.cs.v4.f32 {%0,%1,%2,%3}, [%4];"
                 : "=f"(v.x), "=f"(v.y), "=f"(v.z), "=f"(v.w) : "l"(p));
    return v;
}

// ---------------------------------------------------------------------------
// Kernel 0 (fused prep):
//   blocks [0, 1024):    g_wsum = fp16(mean_l conv_w[l])   (long blocks first)
//   blocks [1024, 2048): g_ax  = fp16(x), 8 float4/thread  (MLP=8)
// ---------------------------------------------------------------------------
__global__ void __launch_bounds__(256)
prep_kernel(const float* __restrict__ x, const float* __restrict__ cw) {
    const int b = blockIdx.x, t = threadIdx.x;
    if (b < WSUM_BLOCKS) {
        const int i4 = b * 256 + t;                    // 0..262143
        const float4* cw4 = (const float4*)cw;
        float4 a0 = ldcs4(&cw4[i4]);
        float4 a1 = ldcs4(&cw4[(HIDDEN*HIDDEN/4) + i4]);
#pragma unroll
        for (int l = 2; l < NLAYERS; l += 2) {
            float4 v0 = ldcs4(&cw4[l       * (HIDDEN*HIDDEN/4) + i4]);
            float4 v1 = ldcs4(&cw4[(l + 1) * (HIDDEN*HIDDEN/4) + i4]);
            a0.x += v0.x; a0.y += v0.y; a0.z += v0.z; a0.w += v0.w;
            a1.x += v1.x; a1.y += v1.y; a1.z += v1.z; a1.w += v1.w;
        }
        const float s = 1.0f / (float)NLAYERS;
        uint2 h;
        h.x = f2_to_h2((a0.x + a1.x) * s, (a0.y + a1.y) * s);
        h.y = f2_to_h2((a0.z + a1.z) * s, (a0.w + a1.w) * s);
        ((uint2*)g_wsum)[i4] = h;
    } else {
        // 8 independent float4 per thread (front-batched -> MLP=8)
        const int base = (b - WSUM_BLOCKS) * 2048 + t;   // float4 index base
        float4 v[8];
#pragma unroll
        for (int i = 0; i < 8; ++i)
            v[i] = ldcs4(&((const float4*)x)[base + i * 256]);
#pragma unroll
        for (int i = 0; i < 8; ++i) {
            uint2 h;
            h.x = f2_to_h2(v[i].x, v[i].y);
            h.y = f2_to_h2(v[i].z, v[i].w);
            ((uint2*)g_ax)[base + i * 256] = h;
        }
    }
}

// ---------------------------------------------------------------------------
// Kernel 1: fp16 GEMM  out[m][n] = sum_k Ax[m][k] * Wsum[n][k]
//   (byte-identical to the proven 62us R3 mainloop)
// ---------------------------------------------------------------------------
__global__ void __launch_bounds__(256, 2)
gemm_kernel(float* __restrict__ out) {
    extern __shared__ char smem[];
    const uint32_t sbase = smem_u32(smem);

    const int tid  = threadIdx.x;
    const int lane = tid & 31;
    const int warp = tid >> 5;
    const int wm   = (warp & 1) * 64;
    const int wn   = (warp >> 1) * 32;
    const int mBase = blockIdx.y * BM;
    const int nBase = blockIdx.x * BN;

    float acc[4][4][4];
#pragma unroll
    for (int mi = 0; mi < 4; ++mi)
#pragma unroll
        for (int ni = 0; ni < 4; ++ni)
#pragma unroll
            for (int c = 0; c < 4; ++c) acc[mi][ni][c] = 0.0f;

    auto load_stage = [&](int s, int k0h) {
        const uint32_t sa = sbase + (uint32_t)s * STAGE;
        const uint32_t sb = sa + A_STAGE;
#pragma unroll
        for (int i = 0; i < 4; ++i) {
            const int c = i * 256 + tid;          // 0..1023
            const int row = c >> 3, ch = c & 7;
            const uint32_t off = (uint32_t)c * 16u;
            cp16(sa + (off ^ ((off >> 3) & 0x70u)),
                 g_ax + (size_t)(mBase + row) * HIDDEN + k0h + ch * 8);
        }
#pragma unroll
        for (int i = 0; i < 4; ++i) {
            const int c = i * 256 + tid;
            const int row = c >> 3, ch = c & 7;
            const uint32_t off = (uint32_t)c * 16u;
            cp16(sb + (off ^ ((off >> 3) & 0x70u)),
                 g_wsum + (size_t)(nBase + row) * HIDDEN + k0h + ch * 8);
        }
        asm volatile("cp.async.commit_group;");
    };

    load_stage(0, 0);
    load_stage(1, BKH);

    for (int kt = 0; kt < KT; ++kt) {
        asm volatile("cp.async.wait_group 1;");
        __syncthreads();
        if (kt + 2 < KT) load_stage((kt + 2) % STAGES, (kt + 2) * BKH);
        else             asm volatile("cp.async.commit_group;");

        const uint32_t sa = sbase + (uint32_t)(kt % STAGES) * STAGE;
        const uint32_t sb = sa + A_STAGE;

#pragma unroll
        for (int kk = 0; kk < 4; ++kk) {
            const uint32_t colb = (uint32_t)(kk * 32 + (lane >> 4) * 16);
            uint32_t af[4][4], bf[2][4];
#pragma unroll
            for (int mi = 0; mi < 4; ++mi) {
                const uint32_t off = (uint32_t)(wm + mi * 16 + (lane & 15)) * ROWB + colb;
                const uint32_t addr = sa + (off ^ ((off >> 3) & 0x70u));
                asm volatile("ldmatrix.sync.aligned.m8n8.x4.shared.b16 {%0,%1,%2,%3}, [%4];"
                             : "=r"(af[mi][0]), "=r"(af[mi][1]), "=r"(af[mi][2]), "=r"(af[mi][3])
                             : "r"(addr));
            }
#pragma unroll
            for (int np = 0; np < 2; ++np) {
                const uint32_t off = (uint32_t)(wn + np * 16 + (lane & 15)) * ROWB + colb;
                const uint32_t addr = sb + (off ^ ((off >> 3) & 0x70u));
                asm volatile("ldmatrix.sync.aligned.m8n8.x4.shared.b16 {%0,%1,%2,%3}, [%4];"
                             : "=r"(bf[np][0]), "=r"(bf[np][1]), "=r"(bf[np][2]), "=r"(bf[np][3])
                             : "r"(addr));
            }
#pragma unroll
            for (int mi = 0; mi < 4; ++mi) {
#pragma unroll
                for (int np = 0; np < 2; ++np) {
                    asm volatile(
                        "mma.sync.aligned.m16n8k16.row.col.f32.f16.f16.f32 "
                        "{%0,%1,%2,%3}, {%4,%5,%6,%7}, {%8,%9}, {%0,%1,%2,%3};"
                        : "+f"(acc[mi][np*2][0]), "+f"(acc[mi][np*2][1]),
                          "+f"(acc[mi][np*2][2]), "+f"(acc[mi][np*2][3])
                        : "r"(af[mi][0]), "r"(af[mi][1]), "r"(af[mi][2]), "r"(af[mi][3]),
                          "r"(bf[np][0]), "r"(bf[np][2]));
                    asm volatile(
                        "mma.sync.aligned.m16n8k16.row.col.f32.f16.f16.f32 "
                        "{%0,%1,%2,%3}, {%4,%5,%6,%7}, {%8,%9}, {%0,%1,%2,%3};"
                        : "+f"(acc[mi][np*2+1][0]), "+f"(acc[mi][np*2+1][1]),
                          "+f"(acc[mi][np*2+1][2]), "+f"(acc[mi][np*2+1][3])
                        : "r"(af[mi][0]), "r"(af[mi][1]), "r"(af[mi][2]), "r"(af[mi][3]),
                          "r"(bf[np][1]), "r"(bf[np][3]));
                }
            }
        }
    }

    // epilogue
    const int r0 = mBase + wm + (lane >> 2);
    const int c0 = nBase + wn + (lane & 3) * 2;
#pragma unroll
    for (int mi = 0; mi < 4; ++mi) {
#pragma unroll
        for (int ni = 0; ni < 4; ++ni) {
            const int r = r0 + mi * 16;
            const int c = c0 + ni * 8;
            *(float2*)(out + (size_t)r * HIDDEN + c)       = make_float2(acc[mi][ni][0], acc[mi][ni][1]);
            *(float2*)(out + (size_t)(r + 8) * HIDDEN + c) = make_float2(acc[mi][ni][2], acc[mi][ni][3]);
        }
    }
}

// ---------------------------------------------------------------------------
// Kernel 2: in-place RMS-norm, one warp per row (barrier-free, MLP=8)
//   x * sqrt(H) / sqrt(sum x^2 + EPS*H) * w
// ---------------------------------------------------------------------------
__global__ void __launch_bounds__(256)
rmsnorm_kernel(float* __restrict__ out, const float* __restrict__ nw) {
    const int wid  = threadIdx.x >> 5;       // warp in block: 0..7
    const int lane = threadIdx.x & 31;
    const int row  = blockIdx.x * 8 + wid;

    float4* p = (float4*)(out + (size_t)row * HIDDEN);

    float4 v[8];
#pragma unroll
    for (int i = 0; i < 8; ++i)
        v[i] = p[lane + i * 32];              // front-batched: MLP=8

    float ss = 0.0f;
#pragma unroll
    for (int i = 0; i < 8; ++i)
        ss += v[i].x*v[i].x + v[i].y*v[i].y + v[i].z*v[i].z + v[i].w*v[i].w;
#pragma unroll
    for (int o = 16; o > 0; o >>= 1) ss += __shfl_xor_sync(0xFFFFFFFFu, ss, o);

    const float sc = 32.0f * rsqrtf(ss + 1.024e-3f);   // sqrt(H)/sqrt(ss+EPS*H)

#pragma unroll
    for (int i = 0; i < 8; ++i) {
        const float4 w = __ldg(&((const float4*)nw)[lane + i * 32]);
        v[i].x *= sc * w.x; v[i].y *= sc * w.y;
        v[i].z *= sc * w.z; v[i].w *= sc * w.w;
        p[lane + i * 32] = v[i];
    }
}

// ---------------------------------------------------------------------------
extern "C" void kernel_launch(void* const* d_in, const int* in_sizes, int n_in,
                              void* d_out, int out_size) {
    const float* x  = (const float*)d_in[0];   // [2,4096,1024] fp32
    const float* cw = (const float*)d_in[1];   // [20,1024,1024] fp32
    const float* nw = (const float*)d_in[2];   // [1024] fp32
    float* out = (float*)d_out;                // [2,4096,1024] fp32
    (void)in_sizes; (void)n_in; (void)out_size;

    prep_kernel<<<WSUM_BLOCKS + X_BLOCKS, 256>>>(x, cw);   // 2048 blocks

    cudaFuncSetAttribute(gemm_kernel, cudaFuncAttributeMaxDynamicSharedMemorySize, SMEM_BYTES);
    dim3 grid(HIDDEN / BN, M_TOTAL / BM);   // (8, 64) = 512 CTAs
    gemm_kernel<<<grid, 256, SMEM_BYTES>>>(out);

    rmsnorm_kernel<<<M_TOTAL / 8, 256>>>(out, nw);
}

// round 16
// speedup vs baseline: 1.0195x; 1.0036x over previous
#include <cuda_runtime.h>
#include <cuda_fp16.h>
#include <cstdint>

#define HIDDEN   1024
#define NLAYERS  20
#define M_TOTAL  8192

// ---- GEMM tiling (fp16 HMMA m16n8k16) ----
#define BM 128
#define BN 128
#define BKH 64                    // K per tile, in halves -> 128B smem rows
#define KT (HIDDEN/BKH)           // 16
#define ROWB 128
#define A_STAGE (BM*ROWB)         // 16384 B
#define B_STAGE (BN*ROWB)         // 16384 B
#define STAGE   (A_STAGE+B_STAGE) // 32768 B
#define STAGES  3
#define SMEM_BYTES (STAGES*STAGE) // 98304 B -> 2 CTAs/SM

#define WSUM_BLOCKS (HIDDEN*HIDDEN/1024)        // 1024
#define X_BLOCKS    (M_TOTAL*HIDDEN/8192)       // 1024 (8 float4 per thread)

__device__ __half g_wsum[HIDDEN*HIDDEN];     // 2 MB  (pre-summed weights, fp16)
__device__ __half g_ax[M_TOTAL*HIDDEN];      // 16 MB (activations, fp16)

// ---------------------------------------------------------------------------
__device__ __forceinline__ uint32_t smem_u32(const void* p) {
    uint32_t a;
    asm("{ .reg .u64 t; cvta.to.shared.u64 t, %1; cvt.u32.u64 %0, t; }" : "=r"(a) : "l"(p));
    return a;
}
__device__ __forceinline__ void cp16(uint32_t saddr, const void* g) {
    asm volatile("cp.async.cg.shared.global [%0], [%1], 16;" :: "r"(saddr), "l"(g));
}
__device__ __forceinline__ uint32_t f2_to_h2(float lo, float hi) {
    uint32_t r;
    asm("cvt.rn.f16x2.f32 %0, %1, %2;" : "=r"(r) : "f"(hi), "f"(lo));
    return r;
}
// streaming (evict-first) float4 load for read-once data
__device__ __forceinline__ float4 ldcs4(const float4* p) {
    float4 v;
    asm volatile("ld.global.cs.v4.f32 {%0,%1,%2,%3}, [%4];"
                 : "=f"(v.x), "=f"(v.y), "=f"(v.z), "=f"(v.w) : "l"(p));
    return v;
}

// ---------------------------------------------------------------------------
// Kernel 0 (fused prep):
//   blocks [0, 1024):    g_wsum = fp16(mean_l conv_w[l])   (long blocks first;
//                        2 accumulator chains, 4 front-batched loads/iter)
//   blocks [1024, 2048): g_ax  = fp16(x), 8 float4/thread  (MLP=8)
// ---------------------------------------------------------------------------
__global__ void __launch_bounds__(256)
prep_kernel(const float* __restrict__ x, const float* __restrict__ cw) {
    const int b = blockIdx.x, t = threadIdx.x;
    if (b < WSUM_BLOCKS) {
        const int i4 = b * 256 + t;                    // 0..262143
        const float4* cw4 = (const float4*)cw;
        const int LSTR = HIDDEN * HIDDEN / 4;
        // chains: a0 <- even layers ; a1 <- odd layers (same order as best run)
        float4 a0 = ldcs4(&cw4[i4]);
        float4 a1 = ldcs4(&cw4[LSTR + i4]);
#pragma unroll
        for (int l = 2; l + 3 < NLAYERS; l += 4) {     // l = 2,6,10,14 -> layers 2..17
            // 4 independent loads, front-batched -> MLP~4-5
            float4 v0 = ldcs4(&cw4[(l + 0) * LSTR + i4]);
            float4 v1 = ldcs4(&cw4[(l + 1) * LSTR + i4]);
            float4 v2 = ldcs4(&cw4[(l + 2) * LSTR + i4]);
            float4 v3 = ldcs4(&cw4[(l + 3) * LSTR + i4]);
            a0.x += v0.x; a0.y += v0.y; a0.z += v0.z; a0.w += v0.w;
            a1.x += v1.x; a1.y += v1.y; a1.z += v1.z; a1.w += v1.w;
            a0.x += v2.x; a0.y += v2.y; a0.z += v2.z; a0.w += v2.w;
            a1.x += v3.x; a1.y += v3.y; a1.z += v3.z; a1.w += v3.w;
        }
        // remainder: layers 18, 19 (each layer added exactly once)
        {
            float4 v0 = ldcs4(&cw4[18 * LSTR + i4]);
            float4 v1 = ldcs4(&cw4[19 * LSTR + i4]);
            a0.x += v0.x; a0.y += v0.y; a0.z += v0.z; a0.w += v0.w;
            a1.x += v1.x; a1.y += v1.y; a1.z += v1.z; a1.w += v1.w;
        }
        const float s = 1.0f / (float)NLAYERS;
        uint2 h;
        h.x = f2_to_h2((a0.x + a1.x) * s, (a0.y + a1.y) * s);
        h.y = f2_to_h2((a0.z + a1.z) * s, (a0.w + a1.w) * s);
        ((uint2*)g_wsum)[i4] = h;
    } else {
        // 8 independent float4 per thread (front-batched -> MLP=8)
        const int base = (b - WSUM_BLOCKS) * 2048 + t;   // float4 index base
        float4 v[8];
#pragma unroll
        for (int i = 0; i < 8; ++i)
            v[i] = ldcs4(&((const float4*)x)[base + i * 256]);
#pragma unroll
        for (int i = 0; i < 8; ++i) {
            uint2 h;
            h.x = f2_to_h2(v[i].x, v[i].y);
            h.y = f2_to_h2(v[i].z, v[i].w);
            ((uint2*)g_ax)[base + i * 256] = h;
        }
    }
}

// ---------------------------------------------------------------------------
// Kernel 1: fp16 GEMM  out[m][n] = sum_k Ax[m][k] * Wsum[n][k]
//   (byte-identical to the proven 62us R3 mainloop)
// ---------------------------------------------------------------------------
__global__ void __launch_bounds__(256, 2)
gemm_kernel(float* __restrict__ out) {
    extern __shared__ char smem[];
    const uint32_t sbase = smem_u32(smem);

    const int tid  = threadIdx.x;
    const int lane = tid & 31;
    const int warp = tid >> 5;
    const int wm   = (warp & 1) * 64;
    const int wn   = (warp >> 1) * 32;
    const int mBase = blockIdx.y * BM;
    const int nBase = blockIdx.x * BN;

    float acc[4][4][4];
#pragma unroll
    for (int mi = 0; mi < 4; ++mi)
#pragma unroll
        for (int ni = 0; ni < 4; ++ni)
#pragma unroll
            for (int c = 0; c < 4; ++c) acc[mi][ni][c] = 0.0f;

    auto load_stage = [&](int s, int k0h) {
        const uint32_t sa = sbase + (uint32_t)s * STAGE;
        const uint32_t sb = sa + A_STAGE;
#pragma unroll
        for (int i = 0; i < 4; ++i) {
            const int c = i * 256 + tid;          // 0..1023
            const int row = c >> 3, ch = c & 7;
            const uint32_t off = (uint32_t)c * 16u;
            cp16(sa + (off ^ ((off >> 3) & 0x70u)),
                 g_ax + (size_t)(mBase + row) * HIDDEN + k0h + ch * 8);
        }
#pragma unroll
        for (int i = 0; i < 4; ++i) {
            const int c = i * 256 + tid;
            const int row = c >> 3, ch = c & 7;
            const uint32_t off = (uint32_t)c * 16u;
            cp16(sb + (off ^ ((off >> 3) & 0x70u)),
                 g_wsum + (size_t)(nBase + row) * HIDDEN + k0h + ch * 8);
        }
        asm volatile("cp.async.commit_group;");
    };

    load_stage(0, 0);
    load_stage(1, BKH);

    for (int kt = 0; kt < KT; ++kt) {
        asm volatile("cp.async.wait_group 1;");
        __syncthreads();
        if (kt + 2 < KT) load_stage((kt + 2) % STAGES, (kt + 2) * BKH);
        else             asm volatile("cp.async.commit_group;");

        const uint32_t sa = sbase + (uint32_t)(kt % STAGES) * STAGE;
        const uint32_t sb = sa + A_STAGE;

#pragma unroll
        for (int kk = 0; kk < 4; ++kk) {
            const uint32_t colb = (uint32_t)(kk * 32 + (lane >> 4) * 16);
            uint32_t af[4][4], bf[2][4];
#pragma unroll
            for (int mi = 0; mi < 4; ++mi) {
                const uint32_t off = (uint32_t)(wm + mi * 16 + (lane & 15)) * ROWB + colb;
                const uint32_t addr = sa + (off ^ ((off >> 3) & 0x70u));
                asm volatile("ldmatrix.sync.aligned.m8n8.x4.shared.b16 {%0,%1,%2,%3}, [%4];"
                             : "=r"(af[mi][0]), "=r"(af[mi][1]), "=r"(af[mi][2]), "=r"(af[mi][3])
                             : "r"(addr));
            }
#pragma unroll
            for (int np = 0; np < 2; ++np) {
                const uint32_t off = (uint32_t)(wn + np * 16 + (lane & 15)) * ROWB + colb;
                const uint32_t addr = sb + (off ^ ((off >> 3) & 0x70u));
                asm volatile("ldmatrix.sync.aligned.m8n8.x4.shared.b16 {%0,%1,%2,%3}, [%4];"
                             : "=r"(bf[np][0]), "=r"(bf[np][1]), "=r"(bf[np][2]), "=r"(bf[np][3])
                             : "r"(addr));
            }
#pragma unroll
            for (int mi = 0; mi < 4; ++mi) {
#pragma unroll
                for (int np = 0; np < 2; ++np) {
                    asm volatile(
                        "mma.sync.aligned.m16n8k16.row.col.f32.f16.f16.f32 "
                        "{%0,%1,%2,%3}, {%4,%5,%6,%7}, {%8,%9}, {%0,%1,%2,%3};"
                        : "+f"(acc[mi][np*2][0]), "+f"(acc[mi][np*2][1]),
                          "+f"(acc[mi][np*2][2]), "+f"(acc[mi][np*2][3])
                        : "r"(af[mi][0]), "r"(af[mi][1]), "r"(af[mi][2]), "r"(af[mi][3]),
                          "r"(bf[np][0]), "r"(bf[np][2]));
                    asm volatile(
                        "mma.sync.aligned.m16n8k16.row.col.f32.f16.f16.f32 "
                        "{%0,%1,%2,%3}, {%4,%5,%6,%7}, {%8,%9}, {%0,%1,%2,%3};"
                        : "+f"(acc[mi][np*2+1][0]), "+f"(acc[mi][np*2+1][1]),
                          "+f"(acc[mi][np*2+1][2]), "+f"(acc[mi][np*2+1][3])
                        : "r"(af[mi][0]), "r"(af[mi][1]), "r"(af[mi][2]), "r"(af[mi][3]),
                          "r"(bf[np][1]), "r"(bf[np][3]));
                }
            }
        }
    }

    // epilogue
    const int r0 = mBase + wm + (lane >> 2);
    const int c0 = nBase + wn + (lane & 3) * 2;
#pragma unroll
    for (int mi = 0; mi < 4; ++mi) {
#pragma unroll
        for (int ni = 0; ni < 4; ++ni) {
            const int r = r0 + mi * 16;
            const int c = c0 + ni * 8;
            *(float2*)(out + (size_t)r * HIDDEN + c)       = make_float2(acc[mi][ni][0], acc[mi][ni][1]);
            *(float2*)(out + (size_t)(r + 8) * HIDDEN + c) = make_float2(acc[mi][ni][2], acc[mi][ni][3]);
        }
    }
}

// ---------------------------------------------------------------------------
// Kernel 2: in-place RMS-norm, one warp per row (barrier-free, MLP=8)
//   x * sqrt(H) / sqrt(sum x^2 + EPS*H) * w
// ---------------------------------------------------------------------------
__global__ void __launch_bounds__(256)
rmsnorm_kernel(float* __restrict__ out, const float* __restrict__ nw) {
    const int wid  = threadIdx.x >> 5;       // warp in block: 0..7
    const int lane = threadIdx.x & 31;
    const int row  = blockIdx.x * 8 + wid;

    float4* p = (float4*)(out + (size_t)row * HIDDEN);

    float4 v[8];
#pragma unroll
    for (int i = 0; i < 8; ++i)
        v[i] = p[lane + i * 32];              // front-batched: MLP=8

    float ss = 0.0f;
#pragma unroll
    for (int i = 0; i < 8; ++i)
        ss += v[i].x*v[i].x + v[i].y*v[i].y + v[i].z*v[i].z + v[i].w*v[i].w;
#pragma unroll
    for (int o = 16; o > 0; o >>= 1) ss += __shfl_xor_sync(0xFFFFFFFFu, ss, o);

    const float sc = 32.0f * rsqrtf(ss + 1.024e-3f);   // sqrt(H)/sqrt(ss+EPS*H)

#pragma unroll
    for (int i = 0; i < 8; ++i) {
        const float4 w = __ldg(&((const float4*)nw)[lane + i * 32]);
        v[i].x *= sc * w.x; v[i].y *= sc * w.y;
        v[i].z *= sc * w.z; v[i].w *= sc * w.w;
        p[lane + i * 32] = v[i];
    }
}

// ---------------------------------------------------------------------------
extern "C" void kernel_launch(void* const* d_in, const int* in_sizes, int n_in,
                              void* d_out, int out_size) {
    const float* x  = (const float*)d_in[0];   // [2,4096,1024] fp32
    const float* cw = (const float*)d_in[1];   // [20,1024,1024] fp32
    const float* nw = (const float*)d_in[2];   // [1024] fp32
    float* out = (float*)d_out;                // [2,4096,1024] fp32
    (void)in_sizes; (void)n_in; (void)out_size;

    prep_kernel<<<WSUM_BLOCKS + X_BLOCKS, 256>>>(x, cw);   // 2048 blocks

    cudaFuncSetAttribute(gemm_kernel, cudaFuncAttributeMaxDynamicSharedMemorySize, SMEM_BYTES);
    dim3 grid(HIDDEN / BN, M_TOTAL / BM);   // (8, 64) = 512 CTAs
    gemm_kernel<<<grid, 256, SMEM_BYTES>>>(out);

    rmsnorm_kernel<<<M_TOTAL / 8, 256>>>(out, nw);
}